// round 2
// baseline (speedup 1.0000x reference)
#include <cuda_runtime.h>
#include <math.h>

#define DDIM 256
#define MAXN 131072
#define MAXK 1024

// ---- scratch (device globals: no allocation allowed) ----
__device__ float  g_cnorm[MAXK];
__device__ int    g_argmin[MAXN];
__device__ int    g_hist[MAXK];
__device__ double g_sse;

// ---------------------------------------------------------------------------
// Kernel Z: zero per-launch scratch (graph replays must be deterministic)
// ---------------------------------------------------------------------------
__global__ void vq_zero_kernel(int K)
{
    int t = blockIdx.x * blockDim.x + threadIdx.x;
    if (t < K) g_hist[t] = 0;
    if (t == 0) g_sse = 0.0;
}

// ---------------------------------------------------------------------------
// Kernel A: codebook squared norms (one warp per code row)
// ---------------------------------------------------------------------------
__global__ void vq_cnorm_kernel(const float* __restrict__ C, int K)
{
    int warp = (blockIdx.x * blockDim.x + threadIdx.x) >> 5;
    int lane = threadIdx.x & 31;
    if (warp >= K) return;
    const float4* cp = (const float4*)(C + (size_t)warp * DDIM);
    float s = 0.f;
#pragma unroll
    for (int i = 0; i < 2; i++) {
        float4 v = cp[lane + i * 32];
        s += v.x * v.x + v.y * v.y + v.z * v.z + v.w * v.w;
    }
#pragma unroll
    for (int o = 16; o > 0; o >>= 1) s += __shfl_down_sync(0xffffffffu, s, o);
    if (lane == 0) g_cnorm[warp] = s;
}

// ---------------------------------------------------------------------------
// Kernel B: fused distance-GEMM + per-row argmin.
// score(n,k) = ||c_k||^2 - 2 * x_n . c_k   (||x||^2 is row-constant)
// BM=128 rows x BN=128 codes tile, BD=16 D-slab, 256 threads, 8x8 microtile.
// Column microtile = {tx*4..+3} u {64+tx*4..+3}  (conflict-free LDS.128).
// ---------------------------------------------------------------------------
#define BM 128
#define BN 128
#define BD 16
#define TM 8

__global__ __launch_bounds__(256, 2) void vq_argmin_kernel(
    const float* __restrict__ X, const float* __restrict__ C, int K)
{
    __shared__ float As[BD][BM];   // [d][row]
    __shared__ float Bs[BD][BN];   // [d][col]

    const int tid  = threadIdx.x;
    const int tx   = tid & 15;
    const int ty   = tid >> 4;
    const int row0 = ty * TM;        // 8 contiguous rows
    const int colA = tx * 4;         // cols colA..colA+3 and 64+colA..+3
    const int brow = blockIdx.x * BM;

    float bestVal[TM];
    int   bestIdx[TM];
#pragma unroll
    for (int i = 0; i < TM; i++) { bestVal[i] = 3.4e38f; bestIdx[i] = 0; }

    for (int kt = 0; kt < K; kt += BN) {
        float acc[TM][8];
#pragma unroll
        for (int i = 0; i < TM; i++)
#pragma unroll
            for (int j = 0; j < 8; j++) acc[i][j] = 0.f;

        for (int dt = 0; dt < DDIM; dt += BD) {
            __syncthreads();   // protect smem from previous iteration's readers
            // each thread loads 2 float4 of A-tile and 2 of B-tile
#pragma unroll
            for (int l = 0; l < 2; l++) {
                int li  = tid + l * 256;   // 0..511
                int r   = li >> 2;         // row within tile
                int seg = li & 3;          // which float4 of the 16-wide slab
                float4 va = *(const float4*)(X + (size_t)(brow + r) * DDIM + dt + seg * 4);
                As[seg * 4 + 0][r] = va.x; As[seg * 4 + 1][r] = va.y;
                As[seg * 4 + 2][r] = va.z; As[seg * 4 + 3][r] = va.w;
                float4 vb = *(const float4*)(C + (size_t)(kt + r) * DDIM + dt + seg * 4);
                Bs[seg * 4 + 0][r] = vb.x; Bs[seg * 4 + 1][r] = vb.y;
                Bs[seg * 4 + 2][r] = vb.z; Bs[seg * 4 + 3][r] = vb.w;
            }
            __syncthreads();
#pragma unroll
            for (int d = 0; d < BD; d++) {
                float a[TM], b[8];
                float4 a0 = *(const float4*)&As[d][row0];
                float4 a1 = *(const float4*)&As[d][row0 + 4];
                a[0]=a0.x; a[1]=a0.y; a[2]=a0.z; a[3]=a0.w;
                a[4]=a1.x; a[5]=a1.y; a[6]=a1.z; a[7]=a1.w;
                float4 b0 = *(const float4*)&Bs[d][colA];
                float4 b1 = *(const float4*)&Bs[d][64 + colA];
                b[0]=b0.x; b[1]=b0.y; b[2]=b0.z; b[3]=b0.w;
                b[4]=b1.x; b[5]=b1.y; b[6]=b1.z; b[7]=b1.w;
#pragma unroll
                for (int i = 0; i < TM; i++)
#pragma unroll
                    for (int j = 0; j < 8; j++)
                        acc[i][j] = fmaf(a[i], b[j], acc[i][j]);
            }
        }
        // score + running argmin; scan j so global cols ascend (first-min tie-break)
#pragma unroll
        for (int j = 0; j < 8; j++) {
            int gcol = kt + ((j < 4) ? (colA + j) : (64 + colA + j - 4));
            float cn = g_cnorm[gcol];
#pragma unroll
            for (int i = 0; i < TM; i++) {
                float s = fmaf(-2.f, acc[i][j], cn);
                if (s < bestVal[i]) { bestVal[i] = s; bestIdx[i] = gcol; }
            }
        }
    }

    // cross-thread reduction over the 16 tx lanes per row (alias tile smem)
    __syncthreads();
    float* rv = &As[0][0];     // 2048 floats
    int*   ri = (int*)&Bs[0][0];
#pragma unroll
    for (int i = 0; i < TM; i++) {
        rv[(row0 + i) * 16 + tx] = bestVal[i];
        ri[(row0 + i) * 16 + tx] = bestIdx[i];
    }
    __syncthreads();
    if (tid < BM) {
        float bv = rv[tid * 16];
        int   bi = ri[tid * 16];
#pragma unroll
        for (int t = 1; t < 16; t++) {
            float v  = rv[tid * 16 + t];
            int   id = ri[tid * 16 + t];
            if (v < bv || (v == bv && id < bi)) { bv = v; bi = id; }
        }
        g_argmin[brow + tid] = bi;
    }
}

// ---------------------------------------------------------------------------
// Kernel C: gather + straight-through output + SSE + histogram.
// quantized_st = x + (q - x) computed exactly as the reference does.
// One warp per row.
// ---------------------------------------------------------------------------
__global__ void vq_output_kernel(const float* __restrict__ X, const float* __restrict__ C,
                                 float* __restrict__ outQ, float* __restrict__ outIdx, int N)
{
    int warp = (blockIdx.x * blockDim.x + threadIdx.x) >> 5;
    int lane = threadIdx.x & 31;
    if (warp >= N) return;
    int idx = g_argmin[warp];
    const float4* xp = (const float4*)(X + (size_t)warp * DDIM);
    const float4* qp = (const float4*)(C + (size_t)idx  * DDIM);
    float4*       op = (float4*)(outQ + (size_t)warp * DDIM);
    double sse = 0.0;
#pragma unroll
    for (int i = 0; i < 2; i++) {
        float4 x = xp[lane + i * 32];
        float4 q = qp[lane + i * 32];
        float dx = q.x - x.x, dy = q.y - x.y, dz = q.z - x.z, dw = q.w - x.w;
        float4 o;
        o.x = x.x + dx; o.y = x.y + dy; o.z = x.z + dz; o.w = x.w + dw;
        op[lane + i * 32] = o;
        sse += (double)dx * dx + (double)dy * dy + (double)dz * dz + (double)dw * dw;
    }
#pragma unroll
    for (int o = 16; o > 0; o >>= 1) sse += __shfl_down_sync(0xffffffffu, sse, o);
    if (lane == 0) {
        atomicAdd(&g_sse, sse);
        atomicAdd(&g_hist[idx], 1);
        outIdx[warp] = (float)idx;
    }
}

// ---------------------------------------------------------------------------
// Kernel D: loss + perplexity scalars
// ---------------------------------------------------------------------------
__global__ void vq_finalize_kernel(float* __restrict__ outScalars, int N, int K)
{
    __shared__ double red[256];
    int t = threadIdx.x;
    double h = 0.0;
    for (int k = t; k < K; k += 256) {
        float p = (float)g_hist[k] / (float)N;
        h += (double)(p * logf(p + 1e-10f));
    }
    red[t] = h;
    __syncthreads();
    for (int s = 128; s > 0; s >>= 1) {
        if (t < s) red[t] += red[t + s];
        __syncthreads();
    }
    if (t == 0) {
        double mean = g_sse / ((double)N * (double)DDIM);
        outScalars[0] = (float)(1.25 * mean);   // q_latent + 0.25 * e_latent (equal fwd)
        outScalars[1] = (float)exp(-red[0]);    // perplexity
    }
}

// ---------------------------------------------------------------------------
extern "C" void kernel_launch(void* const* d_in, const int* in_sizes, int n_in,
                              void* d_out, int out_size)
{
    const float* X = (const float*)d_in[0];   // [N, 256]
    const float* C = (const float*)d_in[1];   // [K, 256]
    const int N = in_sizes[0] / DDIM;         // 131072
    const int K = in_sizes[1] / DDIM;         // 1024

    float* out        = (float*)d_out;
    float* outQ       = out;                      // N*D quantized_st
    float* outIdx     = out + (size_t)N * DDIM;   // N indices (as f32)
    float* outScalars = outIdx + N;               // loss, perplexity

    vq_zero_kernel<<<(K + 255) / 256, 256>>>(K);
    vq_cnorm_kernel<<<(K * 32 + 255) / 256, 256>>>(C, K);
    vq_argmin_kernel<<<N / BM, 256>>>(X, C, K);
    vq_output_kernel<<<(N * 32 + 255) / 256, 256>>>(X, C, outQ, outIdx, N);
    vq_finalize_kernel<<<1, 256>>>(outScalars, N, K);
}

// round 4
// speedup vs baseline: 1.4156x; 1.4156x over previous
#include <cuda_runtime.h>
#include <cuda_bf16.h>
#include <math.h>
#include <stdint.h>

#define DDIM 256
#define MAXN 131072
#define MAXK 1024
#define NPART 16384   // MAXN / 8 rows-per-output-block

// ---------------- device scratch (no allocations allowed) ----------------
__device__ __nv_bfloat16 g_Xhi[MAXN * DDIM];
__device__ __nv_bfloat16 g_Xlo[MAXN * DDIM];
__device__ __nv_bfloat16 g_Chi[MAXK * DDIM];
__device__ __nv_bfloat16 g_Clo[MAXK * DDIM];
__device__ float  g_cnorm[MAXK];
__device__ int2   g_top2[MAXN];
__device__ int    g_hist[MAXK];
__device__ double g_ssep[NPART];

// ---------------- PTX helpers (plain sm_80-class PTX only!) ----------------
__device__ __forceinline__ uint32_t smem_u32(const void* p) {
    uint32_t a;
    asm("{ .reg .u64 t; cvta.to.shared.u64 t, %1; cvt.u32.u64 %0, t; }" : "=r"(a) : "l"(p));
    return a;
}
#define CP_ASYNC16(dst, src) \
    asm volatile("cp.async.cg.shared.global [%0], [%1], 16;" :: "r"(dst), "l"(src))
#define CP_COMMIT()  asm volatile("cp.async.commit_group;" ::: "memory")
#define CP_WAIT(n)   asm volatile("cp.async.wait_group %0;" :: "n"(n) : "memory")

__device__ __forceinline__ void ldm_x4(uint32_t* r, uint32_t addr) {
    asm volatile("ldmatrix.sync.aligned.m8n8.x4.shared.b16 {%0,%1,%2,%3}, [%4];"
                 : "=r"(r[0]), "=r"(r[1]), "=r"(r[2]), "=r"(r[3]) : "r"(addr));
}
__device__ __forceinline__ void mma16816(float* c, const uint32_t* a, const uint32_t* b) {
    asm volatile(
        "mma.sync.aligned.m16n8k16.row.col.f32.bf16.bf16.f32 "
        "{%0,%1,%2,%3}, {%4,%5,%6,%7}, {%8,%9}, {%0,%1,%2,%3};"
        : "+f"(c[0]), "+f"(c[1]), "+f"(c[2]), "+f"(c[3])
        : "r"(a[0]), "r"(a[1]), "r"(a[2]), "r"(a[3]), "r"(b[0]), "r"(b[1]));
}

// ---------------------------------------------------------------------------
__global__ void vq_zero_kernel(int K)
{
    int t = blockIdx.x * blockDim.x + threadIdx.x;
    if (t < K) g_hist[t] = 0;
}

// ---------------------------------------------------------------------------
__global__ void vq_cnorm_kernel(const float* __restrict__ C, int K)
{
    int warp = (blockIdx.x * blockDim.x + threadIdx.x) >> 5;
    int lane = threadIdx.x & 31;
    if (warp >= K) return;
    const float4* cp = (const float4*)(C + (size_t)warp * DDIM);
    float s = 0.f;
#pragma unroll
    for (int i = 0; i < 2; i++) {
        float4 v = cp[lane + i * 32];
        s += v.x * v.x + v.y * v.y + v.z * v.z + v.w * v.w;
    }
#pragma unroll
    for (int o = 16; o > 0; o >>= 1) s += __shfl_down_sync(0xffffffffu, s, o);
    if (lane == 0) g_cnorm[warp] = s;
}

// ---------------------------------------------------------------------------
// fp32 -> bf16 hi/lo split. mode 0: X arrays, mode 1: C arrays.
// ---------------------------------------------------------------------------
__global__ void vq_convert_kernel(const float* __restrict__ src, int mode, int elem_off, int n4)
{
    int t = blockIdx.x * blockDim.x + threadIdx.x;
    if (t >= n4) return;
    float4 v = ((const float4*)src)[t];
    float x[4] = { v.x, v.y, v.z, v.w };
    unsigned short hb[4], lb[4];
#pragma unroll
    for (int i = 0; i < 4; i++) {
        __nv_bfloat16 h = __float2bfloat16(x[i]);
        __nv_bfloat16 l = __float2bfloat16(x[i] - __bfloat162float(h));
        hb[i] = __bfloat16_as_ushort(h);
        lb[i] = __bfloat16_as_ushort(l);
    }
    uint2 ph, pl;
    ph.x = (uint32_t)hb[0] | ((uint32_t)hb[1] << 16);
    ph.y = (uint32_t)hb[2] | ((uint32_t)hb[3] << 16);
    pl.x = (uint32_t)lb[0] | ((uint32_t)lb[1] << 16);
    pl.y = (uint32_t)lb[2] | ((uint32_t)lb[3] << 16);
    __nv_bfloat16* hi = mode ? g_Chi : g_Xhi;
    __nv_bfloat16* lo = mode ? g_Clo : g_Xlo;
    ((uint2*)(hi + elem_off))[t] = ph;
    ((uint2*)(lo + elem_off))[t] = pl;
}

// ---------------------------------------------------------------------------
// HMMA (mma.sync bf16) distance GEMM + per-row top-2 candidates.
// score(n,k) = ||c_k||^2 - 2 x.c ; dot = xhi.chi + xhi.clo + xlo.chi (fp32 acc).
// CTA: 128 rows (A resident in smem), 8 passes of 128 codes, BK=64 slabs,
// 2-stage cp.async pipeline for B. Warps 4(M)x2(N), warp tile 32x64.
// ---------------------------------------------------------------------------
#define SM_CN 0            // 4 KB: cnorm[1024]
#define SM_A  4096         // 128 KB: Ahi 64K | Alo 64K  (row 512B, swizzled)
#define SM_B  135168       // 64 KB: 2 stages x (Bhi 16K | Blo 16K)
#define SMEM_BYTES 200704

__global__ __launch_bounds__(256, 1) void vq_gemm_kernel()
{
    extern __shared__ char smem[];
    const uint32_t sb = smem_u32(smem);
    const int tid  = threadIdx.x;
    const int lane = tid & 31;
    const int wid  = tid >> 5;
    const int wm0  = (wid >> 1) * 32;     // warp M origin (4 warps)
    const int wn0  = (wid & 1) * 64;      // warp N origin (2 warps)
    const int brow = blockIdx.x * 128;

    // ---- load cnorm (4 KB) + A resident tiles (128 KB) via cp.async ----
    {
        uint32_t d = sb + SM_CN + tid * 16;
        CP_ASYNC16(d, g_cnorm + tid * 4);
    }
#pragma unroll
    for (int it = 0; it < 16; it++) {
        int li  = tid + it * 256;           // 0..4095
        int row = li >> 5, u = li & 31;
        uint32_t sw = (uint32_t)((u & 24) | ((u & 7) ^ (row & 7)));
        uint32_t d  = sb + SM_A + row * 512 + sw * 16;
        const size_t src = (size_t)(brow + row) * DDIM + u * 8;
        CP_ASYNC16(d,         g_Xhi + src);
        CP_ASYNC16(d + 65536, g_Xlo + src);
    }
    CP_COMMIT();

    // per-thread running top-2 for 4 row-slots (im*2 + acchalf)
    float bv1[4], bv2[4];
    int   bi1[4], bi2[4];
#pragma unroll
    for (int i = 0; i < 4; i++) { bv1[i] = 3.4e38f; bv2[i] = 3.4e38f; bi1[i] = 0; bi2[i] = 1; }

    CP_WAIT(0);
    __syncthreads();

    const float* cn = (const float*)smem;   // SM_CN

    for (int p = 0; p < 8; p++) {
        const int kt = p * 128;

        float acc[2][8][4];
#pragma unroll
        for (int im = 0; im < 2; im++)
#pragma unroll
            for (int jn = 0; jn < 8; jn++)
#pragma unroll
                for (int e = 0; e < 4; e++) acc[im][jn][e] = 0.f;

        // prologue: load slab 0 into stage 0
        {
#pragma unroll
            for (int it = 0; it < 4; it++) {
                int li = tid + it * 256;          // 0..1023
                int code = li >> 3, u = li & 7;
                uint32_t d = sb + SM_B + code * 128 + (uint32_t)((u ^ (code & 7)) * 16);
                const size_t src = (size_t)(kt + code) * DDIM + u * 8;
                CP_ASYNC16(d,         g_Chi + src);
                CP_ASYNC16(d + 16384, g_Clo + src);
            }
            CP_COMMIT();
        }

#pragma unroll
        for (int s = 0; s < 4; s++) {
            const int st = s & 1;
            if (s < 3) {        // prefetch next slab into other stage
                const int ns = s + 1, nst = ns & 1;
#pragma unroll
                for (int it = 0; it < 4; it++) {
                    int li = tid + it * 256;
                    int code = li >> 3, u = li & 7;
                    uint32_t d = sb + SM_B + nst * 32768 + code * 128
                               + (uint32_t)((u ^ (code & 7)) * 16);
                    const size_t src = (size_t)(kt + code) * DDIM + ns * 64 + u * 8;
                    CP_ASYNC16(d,         g_Chi + src);
                    CP_ASYNC16(d + 16384, g_Clo + src);
                }
                CP_COMMIT();
                CP_WAIT(1);
            } else {
                CP_WAIT(0);
            }
            __syncthreads();

            // ---- compute slab s: 4 k-steps of k16 ----
#pragma unroll
            for (int ksl = 0; ksl < 4; ksl++) {
                uint32_t ah[8], al[8], bh[16], bl[16];
                const int uA = s * 8 + ksl * 2 + (lane >> 4);
#pragma unroll
                for (int im = 0; im < 2; im++) {
                    int row = wm0 + im * 16 + (lane & 15);
                    uint32_t sw = (uint32_t)((uA & 24) | ((uA & 7) ^ (row & 7)));
                    uint32_t ad = sb + SM_A + row * 512 + sw * 16;
                    ldm_x4(&ah[im * 4], ad);
                    ldm_x4(&al[im * 4], ad + 65536);
                }
                const int uB = ksl * 2 + ((lane >> 3) & 1);
#pragma unroll
                for (int j4 = 0; j4 < 4; j4++) {
                    int code = wn0 + j4 * 16 + ((lane >> 4) * 8) + (lane & 7);
                    uint32_t bd = sb + SM_B + st * 32768 + code * 128
                                + (uint32_t)(((uB ^ (code & 7))) * 16);
                    ldm_x4(&bh[j4 * 4], bd);
                    ldm_x4(&bl[j4 * 4], bd + 16384);
                }
#pragma unroll
                for (int im = 0; im < 2; im++)
#pragma unroll
                    for (int jn = 0; jn < 8; jn++) {
                        const int bi = (jn >> 1) * 4 + (jn & 1) * 2;
                        mma16816(acc[im][jn], &ah[im * 4], &bh[bi]);   // hi.hi
                        mma16816(acc[im][jn], &ah[im * 4], &bl[bi]);   // hi.lo
                        mma16816(acc[im][jn], &al[im * 4], &bh[bi]);   // lo.hi
                    }
            }
            __syncthreads();   // stage consumed before it is refilled (s+2)
        }

        // ---- epilogue: scores + running top-2 ----
#pragma unroll
        for (int im = 0; im < 2; im++)
#pragma unroll
            for (int jn = 0; jn < 8; jn++)
#pragma unroll
                for (int e = 0; e < 4; e++) {
                    const int rs  = im * 2 + (e >> 1);
                    const int col = kt + wn0 + jn * 8 + (lane & 3) * 2 + (e & 1);
                    float s = fmaf(-2.f, acc[im][jn][e], cn[col]);
                    if (s < bv1[rs])      { bv2[rs] = bv1[rs]; bi2[rs] = bi1[rs];
                                            bv1[rs] = s;       bi1[rs] = col; }
                    else if (s < bv2[rs]) { bv2[rs] = s;       bi2[rs] = col; }
                }
    }

    // ---- final cross-thread top-2 merge (reuse B stage smem) ----
    __syncthreads();
    float* rv = (float*)(smem + SM_B);        // [128][8][2]
    int*   ri = (int*)(smem + SM_B + 8192);   // [128][8][2]
    const int cid = (wid & 1) * 4 + (lane & 3);
#pragma unroll
    for (int im = 0; im < 2; im++)
#pragma unroll
        for (int half = 0; half < 2; half++) {
            const int rs  = im * 2 + half;
            const int row = wm0 + im * 16 + (lane >> 2) + half * 8;
            rv[(row * 8 + cid) * 2 + 0] = bv1[rs];
            rv[(row * 8 + cid) * 2 + 1] = bv2[rs];
            ri[(row * 8 + cid) * 2 + 0] = bi1[rs];
            ri[(row * 8 + cid) * 2 + 1] = bi2[rs];
        }
    __syncthreads();
    if (tid < 128) {
        float b1 = 3.4e38f, b2 = 3.4e38f;
        int   i1 = 0, i2 = 1;
#pragma unroll
        for (int c = 0; c < 16; c++) {
            float v = rv[(tid * 8) * 2 + c];
            int   i = ri[(tid * 8) * 2 + c];
            if (v < b1 || (v == b1 && i < i1)) { b2 = b1; i2 = i1; b1 = v; i1 = i; }
            else if (v < b2 || (v == b2 && i < i2)) { b2 = v; i2 = i; }
        }
        g_top2[brow + tid] = make_int2(i1, i2);
    }
}

// ---------------------------------------------------------------------------
// Exact fp32 re-rank of the 2 candidates + gather + straight-through output
// + SSE partials + histogram. One warp per row; per-block SSE partial.
// ---------------------------------------------------------------------------
__global__ __launch_bounds__(256) void vq_output_kernel(
    const float* __restrict__ X, const float* __restrict__ C,
    float* __restrict__ outQ, float* __restrict__ outIdx, int N)
{
    __shared__ double wsse[8];
    int gw   = (blockIdx.x * 256 + threadIdx.x) >> 5;
    int lane = threadIdx.x & 31;
    int wib  = threadIdx.x >> 5;

    if (gw < N) {
        int2 cd = g_top2[gw];
        const float4* xp = (const float4*)(X + (size_t)gw   * DDIM);
        const float4* ap = (const float4*)(C + (size_t)cd.x * DDIM);
        const float4* bp = (const float4*)(C + (size_t)cd.y * DDIM);
        float4 x0 = xp[lane], x1 = xp[lane + 32];
        float4 a0 = ap[lane], a1 = ap[lane + 32];
        float4 b0 = bp[lane], b1 = bp[lane + 32];

        float d1 = x0.x*a0.x + x0.y*a0.y + x0.z*a0.z + x0.w*a0.w
                 + x1.x*a1.x + x1.y*a1.y + x1.z*a1.z + x1.w*a1.w;
        float d2 = x0.x*b0.x + x0.y*b0.y + x0.z*b0.z + x0.w*b0.w
                 + x1.x*b1.x + x1.y*b1.y + x1.z*b1.z + x1.w*b1.w;
#pragma unroll
        for (int o = 16; o > 0; o >>= 1) {
            d1 += __shfl_xor_sync(0xffffffffu, d1, o);
            d2 += __shfl_xor_sync(0xffffffffu, d2, o);
        }
        float s1 = g_cnorm[cd.x] - 2.f * d1;
        float s2 = g_cnorm[cd.y] - 2.f * d2;
        bool p2 = (s2 < s1) || (s2 == s1 && cd.y < cd.x);
        float4 q0 = p2 ? b0 : a0;
        float4 q1 = p2 ? b1 : a1;
        int idx = p2 ? cd.y : cd.x;

        float4 o0, o1;
        double sse = 0.0;
        float dx;
        dx = q0.x - x0.x; o0.x = x0.x + dx; sse += (double)dx * dx;
        dx = q0.y - x0.y; o0.y = x0.y + dx; sse += (double)dx * dx;
        dx = q0.z - x0.z; o0.z = x0.z + dx; sse += (double)dx * dx;
        dx = q0.w - x0.w; o0.w = x0.w + dx; sse += (double)dx * dx;
        dx = q1.x - x1.x; o1.x = x1.x + dx; sse += (double)dx * dx;
        dx = q1.y - x1.y; o1.y = x1.y + dx; sse += (double)dx * dx;
        dx = q1.z - x1.z; o1.z = x1.z + dx; sse += (double)dx * dx;
        dx = q1.w - x1.w; o1.w = x1.w + dx; sse += (double)dx * dx;

        float4* op = (float4*)(outQ + (size_t)gw * DDIM);
        op[lane] = o0;
        op[lane + 32] = o1;

#pragma unroll
        for (int o = 16; o > 0; o >>= 1) sse += __shfl_down_sync(0xffffffffu, sse, o);
        if (lane == 0) {
            wsse[wib] = sse;
            atomicAdd(&g_hist[idx], 1);
            outIdx[gw] = (float)idx;
        }
    } else if (lane == 0) {
        wsse[wib] = 0.0;
    }
    __syncthreads();
    if (threadIdx.x == 0) {
        double s = 0.0;
#pragma unroll
        for (int i = 0; i < 8; i++) s += wsse[i];
        g_ssep[blockIdx.x] = s;
    }
}

// ---------------------------------------------------------------------------
__global__ void vq_finalize_kernel(float* __restrict__ outS, int N, int K)
{
    __shared__ double red[256];
    int t = threadIdx.x;
    double s = 0.0;
    for (int i = t; i < NPART; i += 256) s += g_ssep[i];
    red[t] = s;
    __syncthreads();
    for (int st = 128; st > 0; st >>= 1) { if (t < st) red[t] += red[t + st]; __syncthreads(); }
    double sseTot = red[0];
    __syncthreads();

    double h = 0.0;
    for (int k = t; k < K; k += 256) {
        float pr = (float)g_hist[k] / (float)N;
        h += (double)(pr * logf(pr + 1e-10f));
    }
    red[t] = h;
    __syncthreads();
    for (int st = 128; st > 0; st >>= 1) { if (t < st) red[t] += red[t + st]; __syncthreads(); }
    if (t == 0) {
        double mean = sseTot / ((double)N * (double)DDIM);
        outS[0] = (float)(1.25 * mean);
        outS[1] = (float)exp(-red[0]);
    }
}

// ---------------------------------------------------------------------------
extern "C" void kernel_launch(void* const* d_in, const int* in_sizes, int n_in,
                              void* d_out, int out_size)
{
    const float* X = (const float*)d_in[0];   // [N, 256]
    const float* C = (const float*)d_in[1];   // [K, 256]
    const int N = in_sizes[0] / DDIM;         // 131072
    const int K = in_sizes[1] / DDIM;         // 1024

    float* out        = (float*)d_out;
    float* outQ       = out;                      // N*D quantized_st
    float* outIdx     = out + (size_t)N * DDIM;   // N indices (as f32)
    float* outScalars = outIdx + N;               // loss, perplexity

    static bool attr_set = false;
    if (!attr_set) {
        cudaFuncSetAttribute(vq_gemm_kernel,
                             cudaFuncAttributeMaxDynamicSharedMemorySize, SMEM_BYTES);
        attr_set = true;
    }

    const int n4C  = K * DDIM / 4;            // 65536
    const int n4Xh = N * DDIM / 8;            // 4194304 (half of X, in float4s)

    vq_zero_kernel<<<(K + 255) / 256, 256>>>(K);                              // 1
    vq_cnorm_kernel<<<(K * 32 + 255) / 256, 256>>>(C, K);                     // 2
    vq_convert_kernel<<<(n4C + 255) / 256, 256>>>(C, 1, 0, n4C);              // 3
    vq_convert_kernel<<<(n4Xh + 255) / 256, 256>>>(X, 0, 0, n4Xh);            // 4
    vq_convert_kernel<<<(n4Xh + 255) / 256, 256>>>(X + (size_t)n4Xh * 4, 0,
                                                   n4Xh * 4, n4Xh);           // 5
    vq_gemm_kernel<<<N / 128, 256, SMEM_BYTES>>>();                           // 6 (ncu -s 5)
    vq_output_kernel<<<N / 8, 256>>>(X, C, outQ, outIdx, N);                  // 7
    vq_finalize_kernel<<<1, 256>>>(outScalars, N, K);                         // 8
}

// round 7
// speedup vs baseline: 3.4291x; 2.4224x over previous
#include <cuda_runtime.h>
#include <cuda_bf16.h>
#include <math.h>
#include <stdint.h>

#define DDIM 256
#define MAXN 131072
#define MAXK 1024
#define NPART 16384   // MAXN / 8 rows-per-output-block

// ---------------- device scratch (no allocations allowed) ----------------
__device__ __nv_bfloat16 g_Xhi[MAXN * DDIM];
__device__ __nv_bfloat16 g_Chi[MAXK * DDIM];
__device__ float  g_cnorm[MAXK];
__device__ int    g_cand[MAXN * 8];     // 6 candidates + 2 pad per row
__device__ int    g_hist[MAXK];
__device__ double g_ssep[NPART];

// ---------------- PTX helpers (plain sm_80-class PTX only) ----------------
__device__ __forceinline__ uint32_t smem_u32(const void* p) {
    uint32_t a;
    asm("{ .reg .u64 t; cvta.to.shared.u64 t, %1; cvt.u32.u64 %0, t; }" : "=r"(a) : "l"(p));
    return a;
}
#define CP_ASYNC16(dst, src) \
    asm volatile("cp.async.cg.shared.global [%0], [%1], 16;" :: "r"(dst), "l"(src))
#define CP_COMMIT()  asm volatile("cp.async.commit_group;" ::: "memory")
#define CP_WAIT(n)   asm volatile("cp.async.wait_group %0;" :: "n"(n) : "memory")

__device__ __forceinline__ void ldm_x4(uint32_t* r, uint32_t addr) {
    asm volatile("ldmatrix.sync.aligned.m8n8.x4.shared.b16 {%0,%1,%2,%3}, [%4];"
                 : "=r"(r[0]), "=r"(r[1]), "=r"(r[2]), "=r"(r[3]) : "r"(addr));
}
__device__ __forceinline__ void mma16816(float* c, const uint32_t* a, const uint32_t* b) {
    asm volatile(
        "mma.sync.aligned.m16n8k16.row.col.f32.bf16.bf16.f32 "
        "{%0,%1,%2,%3}, {%4,%5,%6,%7}, {%8,%9}, {%0,%1,%2,%3};"
        : "+f"(c[0]), "+f"(c[1]), "+f"(c[2]), "+f"(c[3])
        : "r"(a[0]), "r"(a[1]), "r"(a[2]), "r"(a[3]), "r"(b[0]), "r"(b[1]));
}

// ---------------------------------------------------------------------------
__global__ void vq_zero_kernel(int K)
{
    int t = blockIdx.x * blockDim.x + threadIdx.x;
    if (t < K) g_hist[t] = 0;
}

// ---------------------------------------------------------------------------
__global__ void vq_cnorm_kernel(const float* __restrict__ C, int K)
{
    int warp = (blockIdx.x * blockDim.x + threadIdx.x) >> 5;
    int lane = threadIdx.x & 31;
    if (warp >= K) return;
    const float4* cp = (const float4*)(C + (size_t)warp * DDIM);
    float s = 0.f;
#pragma unroll
    for (int i = 0; i < 2; i++) {
        float4 v = cp[lane + i * 32];
        s += v.x * v.x + v.y * v.y + v.z * v.z + v.w * v.w;
    }
#pragma unroll
    for (int o = 16; o > 0; o >>= 1) s += __shfl_down_sync(0xffffffffu, s, o);
    if (lane == 0) g_cnorm[warp] = s;
}

// ---------------------------------------------------------------------------
// fp32 -> bf16 (round-to-nearest). mode 0: X, mode 1: C.
// ---------------------------------------------------------------------------
__global__ void vq_convert_kernel(const float* __restrict__ src, int mode, int elem_off, int n4)
{
    int t = blockIdx.x * blockDim.x + threadIdx.x;
    if (t >= n4) return;
    float4 v = ((const float4*)src)[t];
    uint2 ph;
    ph.x = (uint32_t)__bfloat16_as_ushort(__float2bfloat16(v.x))
         | ((uint32_t)__bfloat16_as_ushort(__float2bfloat16(v.y)) << 16);
    ph.y = (uint32_t)__bfloat16_as_ushort(__float2bfloat16(v.z))
         | ((uint32_t)__bfloat16_as_ushort(__float2bfloat16(v.w)) << 16);
    __nv_bfloat16* hi = mode ? g_Chi : g_Xhi;
    ((uint2*)(hi + elem_off))[t] = ph;
}

// ---------------------------------------------------------------------------
// bf16 HMMA distance GEMM + per-row top-6 candidates (single product).
// score(n,k) ~= ||c_k||^2 - 2 xhi.chi  (fp32 accum; error sigma ~0.05,
// order-stat gaps ~16 -> exact argmin is in top-6 w.p. ~1).
// CTA: 128 rows resident, 8 passes of 128 codes, BK=64 slabs, 2-stage
// cp.async pipe. Warps 4(M)x2(N), warp tile 32x64. Per-thread top-3,
// CTA merge -> top-6 per row.
// ---------------------------------------------------------------------------
#define SM_CN 0            // 4 KB cnorm
#define SM_A  4096         // 64 KB: A hi (row 512B, swizzled)
#define SM_B  69632        // 32 KB: 2 stages x 16 KB
#define SMEM_BYTES 102400

__global__ __launch_bounds__(256, 2) void vq_gemm_kernel()
{
    extern __shared__ char smem[];
    const uint32_t sb = smem_u32(smem);
    const int tid  = threadIdx.x;
    const int lane = tid & 31;
    const int wid  = tid >> 5;
    const int wm0  = (wid >> 1) * 32;     // warp M origin (4)
    const int wn0  = (wid & 1) * 64;      // warp N origin (2)
    const int brow = blockIdx.x * 128;

    // ---- cnorm (4 KB) + resident A (64 KB) via cp.async ----
    CP_ASYNC16(sb + SM_CN + tid * 16, g_cnorm + tid * 4);
#pragma unroll
    for (int it = 0; it < 16; it++) {
        int li  = tid + it * 256;           // 0..4095
        int row = li >> 5, u = li & 31;
        uint32_t sw = (uint32_t)((u & 24) | ((u & 7) ^ (row & 7)));
        CP_ASYNC16(sb + SM_A + row * 512 + sw * 16,
                   g_Xhi + (size_t)(brow + row) * DDIM + u * 8);
    }
    CP_COMMIT();

    // per-thread top-3 for 4 row-slots
    float tv[4][3];
    int   ti[4][3];
#pragma unroll
    for (int i = 0; i < 4; i++)
#pragma unroll
        for (int j = 0; j < 3; j++) { tv[i][j] = 3.4e38f; ti[i][j] = 0x7FFFFFFF; }

    CP_WAIT(0);
    __syncthreads();

    const float* cn = (const float*)smem;

    for (int p = 0; p < 8; p++) {
        const int kt = p * 128;

        float acc[2][8][4];
#pragma unroll
        for (int im = 0; im < 2; im++)
#pragma unroll
            for (int jn = 0; jn < 8; jn++)
#pragma unroll
                for (int e = 0; e < 4; e++) acc[im][jn][e] = 0.f;

        // prologue: slab 0 -> stage 0
#pragma unroll
        for (int it = 0; it < 4; it++) {
            int li = tid + it * 256;
            int code = li >> 3, u = li & 7;
            CP_ASYNC16(sb + SM_B + code * 128 + (uint32_t)((u ^ (code & 7)) * 16),
                       g_Chi + (size_t)(kt + code) * DDIM + u * 8);
        }
        CP_COMMIT();

#pragma unroll
        for (int s = 0; s < 4; s++) {
            const int st = s & 1;
            if (s < 3) {
                const int ns = s + 1, nst = ns & 1;
#pragma unroll
                for (int it = 0; it < 4; it++) {
                    int li = tid + it * 256;
                    int code = li >> 3, u = li & 7;
                    CP_ASYNC16(sb + SM_B + nst * 16384 + code * 128
                               + (uint32_t)((u ^ (code & 7)) * 16),
                               g_Chi + (size_t)(kt + code) * DDIM + ns * 64 + u * 8);
                }
                CP_COMMIT();
                CP_WAIT(1);
            } else {
                CP_WAIT(0);
            }
            __syncthreads();

#pragma unroll
            for (int ksl = 0; ksl < 4; ksl++) {
                uint32_t ah[8], bh[16];
                const int uA = s * 8 + ksl * 2 + (lane >> 4);
#pragma unroll
                for (int im = 0; im < 2; im++) {
                    int row = wm0 + im * 16 + (lane & 15);
                    uint32_t sw = (uint32_t)((uA & 24) | ((uA & 7) ^ (row & 7)));
                    ldm_x4(&ah[im * 4], sb + SM_A + row * 512 + sw * 16);
                }
                const int uB = ksl * 2 + ((lane >> 3) & 1);
#pragma unroll
                for (int j4 = 0; j4 < 4; j4++) {
                    int code = wn0 + j4 * 16 + ((lane >> 4) * 8) + (lane & 7);
                    ldm_x4(&bh[j4 * 4], sb + SM_B + st * 16384 + code * 128
                                        + (uint32_t)((uB ^ (code & 7)) * 16));
                }
#pragma unroll
                for (int im = 0; im < 2; im++)
#pragma unroll
                    for (int jn = 0; jn < 8; jn++)
                        mma16816(acc[im][jn], &ah[im * 4],
                                 &bh[(jn >> 1) * 4 + (jn & 1) * 2]);
            }
            __syncthreads();
        }

        // ---- epilogue: scores + per-thread running top-3 ----
#pragma unroll
        for (int im = 0; im < 2; im++)
#pragma unroll
            for (int jn = 0; jn < 8; jn++)
#pragma unroll
                for (int e = 0; e < 4; e++) {
                    const int rs  = im * 2 + (e >> 1);
                    const int col = kt + wn0 + jn * 8 + (lane & 3) * 2 + (e & 1);
                    float s = fmaf(-2.f, acc[im][jn][e], cn[col]);
                    if (s < tv[rs][2]) {
                        if (s < tv[rs][1]) {
                            tv[rs][2] = tv[rs][1]; ti[rs][2] = ti[rs][1];
                            if (s < tv[rs][0]) {
                                tv[rs][1] = tv[rs][0]; ti[rs][1] = ti[rs][0];
                                tv[rs][0] = s;         ti[rs][0] = col;
                            } else { tv[rs][1] = s; ti[rs][1] = col; }
                        } else { tv[rs][2] = s; ti[rs][2] = col; }
                    }
                }
    }

    // ---- CTA merge: 8 contributors x 3 -> top-6 per row ----
    __syncthreads();
    float* rv = (float*)(smem + SM_B);          // [128][8][3]
    int*   ri = (int*)(smem + SM_B + 12288);    // [128][8][3]
    const int cid = (wid & 1) * 4 + (lane & 3);
#pragma unroll
    for (int im = 0; im < 2; im++)
#pragma unroll
        for (int half = 0; half < 2; half++) {
            const int rs  = im * 2 + half;
            const int row = wm0 + im * 16 + (lane >> 2) + half * 8;
#pragma unroll
            for (int sl = 0; sl < 3; sl++) {
                rv[(row * 8 + cid) * 3 + sl] = tv[rs][sl];
                ri[(row * 8 + cid) * 3 + sl] = ti[rs][sl];
            }
        }
    __syncthreads();
    if (tid < 128) {
        float v[6]; int ix[6];
#pragma unroll
        for (int j = 0; j < 6; j++) { v[j] = 3.4e38f; ix[j] = 0x7FFFFFFF; }
        for (int c = 0; c < 24; c++) {
            float val = rv[tid * 24 + c];
            int   id  = ri[tid * 24 + c];
            if (val < v[5] || (val == v[5] && id < ix[5])) {
                v[5] = val; ix[5] = id;
#pragma unroll
                for (int j = 5; j > 0; j--) {
                    if (v[j] < v[j-1] || (v[j] == v[j-1] && ix[j] < ix[j-1])) {
                        float tv_ = v[j]; v[j] = v[j-1]; v[j-1] = tv_;
                        int   ti_ = ix[j]; ix[j] = ix[j-1]; ix[j-1] = ti_;
                    }
                }
            }
        }
        int* gc = g_cand + (size_t)(brow + tid) * 8;
        int4 w0 = make_int4(ix[0], ix[1], ix[2], ix[3]);
        int4 w1 = make_int4(ix[4], ix[5], ix[0], ix[0]);
        ((int4*)gc)[0] = w0;
        ((int4*)gc)[1] = w1;
    }
}

// ---------------------------------------------------------------------------
// Exact fp32 re-rank of 6 candidates + gather + straight-through output
// + SSE partials + histogram. One warp per row.
// ---------------------------------------------------------------------------
__global__ __launch_bounds__(256) void vq_output_kernel(
    const float* __restrict__ X, const float* __restrict__ C,
    float* __restrict__ outQ, float* __restrict__ outIdx, int N)
{
    __shared__ double wsse[8];
    int gw   = (blockIdx.x * 256 + threadIdx.x) >> 5;
    int lane = threadIdx.x & 31;
    int wib  = threadIdx.x >> 5;

    if (gw < N) {
        const int4 c0 = ((const int4*)(g_cand + (size_t)gw * 8))[0];
        const int4 c1 = ((const int4*)(g_cand + (size_t)gw * 8))[1];
        int cand[6] = { c0.x, c0.y, c0.z, c0.w, c1.x, c1.y };

        const float4* xp = (const float4*)(X + (size_t)gw * DDIM);
        float4 x0 = xp[lane], x1 = xp[lane + 32];

        float bestS = 3.4e38f;
        int   bestI = 0x7FFFFFFF;
        float4 bq0 = x0, bq1 = x1;
#pragma unroll
        for (int j = 0; j < 6; j++) {
            const int idx = cand[j];
            const float4* cp = (const float4*)(C + (size_t)idx * DDIM);
            float4 q0 = cp[lane], q1 = cp[lane + 32];
            float d = x0.x*q0.x + x0.y*q0.y + x0.z*q0.z + x0.w*q0.w
                    + x1.x*q1.x + x1.y*q1.y + x1.z*q1.z + x1.w*q1.w;
#pragma unroll
            for (int o = 16; o > 0; o >>= 1) d += __shfl_xor_sync(0xffffffffu, d, o);
            float s = g_cnorm[idx] - 2.f * d;
            bool better = (s < bestS) || (s == bestS && idx < bestI);
            if (better) { bestS = s; bestI = idx; bq0 = q0; bq1 = q1; }
        }

        float4 o0, o1;
        double sse = 0.0;
        float dx;
        dx = bq0.x - x0.x; o0.x = x0.x + dx; sse += (double)dx * dx;
        dx = bq0.y - x0.y; o0.y = x0.y + dx; sse += (double)dx * dx;
        dx = bq0.z - x0.z; o0.z = x0.z + dx; sse += (double)dx * dx;
        dx = bq0.w - x0.w; o0.w = x0.w + dx; sse += (double)dx * dx;
        dx = bq1.x - x1.x; o1.x = x1.x + dx; sse += (double)dx * dx;
        dx = bq1.y - x1.y; o1.y = x1.y + dx; sse += (double)dx * dx;
        dx = bq1.z - x1.z; o1.z = x1.z + dx; sse += (double)dx * dx;
        dx = bq1.w - x1.w; o1.w = x1.w + dx; sse += (double)dx * dx;

        float4* op = (float4*)(outQ + (size_t)gw * DDIM);
        op[lane] = o0;
        op[lane + 32] = o1;

#pragma unroll
        for (int o = 16; o > 0; o >>= 1) sse += __shfl_down_sync(0xffffffffu, sse, o);
        if (lane == 0) {
            wsse[wib] = sse;
            atomicAdd(&g_hist[bestI], 1);
            outIdx[gw] = (float)bestI;
        }
    } else if (lane == 0) {
        wsse[wib] = 0.0;
    }
    __syncthreads();
    if (threadIdx.x == 0) {
        double s = 0.0;
#pragma unroll
        for (int i = 0; i < 8; i++) s += wsse[i];
        g_ssep[blockIdx.x] = s;
    }
}

// ---------------------------------------------------------------------------
__global__ void vq_finalize_kernel(float* __restrict__ outS, int N, int K)
{
    __shared__ double red[256];
    int t = threadIdx.x;
    double s = 0.0;
    for (int i = t; i < NPART; i += 256) s += g_ssep[i];
    red[t] = s;
    __syncthreads();
    for (int st = 128; st > 0; st >>= 1) { if (t < st) red[t] += red[t + st]; __syncthreads(); }
    double sseTot = red[0];
    __syncthreads();

    double h = 0.0;
    for (int k = t; k < K; k += 256) {
        float pr = (float)g_hist[k] / (float)N;
        h += (double)(pr * logf(pr + 1e-10f));
    }
    red[t] = h;
    __syncthreads();
    for (int st = 128; st > 0; st >>= 1) { if (t < st) red[t] += red[t + st]; __syncthreads(); }
    if (t == 0) {
        double mean = sseTot / ((double)N * (double)DDIM);
        outS[0] = (float)(1.25 * mean);
        outS[1] = (float)exp(-red[0]);
    }
}

// ---------------------------------------------------------------------------
extern "C" void kernel_launch(void* const* d_in, const int* in_sizes, int n_in,
                              void* d_out, int out_size)
{
    const float* X = (const float*)d_in[0];   // [N, 256]
    const float* C = (const float*)d_in[1];   // [K, 256]
    const int N = in_sizes[0] / DDIM;         // 131072
    const int K = in_sizes[1] / DDIM;         // 1024

    float* out        = (float*)d_out;
    float* outQ       = out;                      // N*D quantized_st
    float* outIdx     = out + (size_t)N * DDIM;   // N indices (as f32)
    float* outScalars = outIdx + N;               // loss, perplexity

    static bool attr_set = false;
    if (!attr_set) {
        cudaFuncSetAttribute(vq_gemm_kernel,
                             cudaFuncAttributeMaxDynamicSharedMemorySize, SMEM_BYTES);
        attr_set = true;
    }

    const int n4C  = K * DDIM / 4;            // 65536
    const int n4Xh = N * DDIM / 8;            // half of X in float4s

    vq_zero_kernel<<<(K + 255) / 256, 256>>>(K);                              // 1
    vq_cnorm_kernel<<<(K * 32 + 255) / 256, 256>>>(C, K);                     // 2
    vq_convert_kernel<<<(n4C + 255) / 256, 256>>>(C, 1, 0, n4C);              // 3
    vq_convert_kernel<<<(n4Xh + 255) / 256, 256>>>(X, 0, 0, n4Xh);            // 4
    vq_convert_kernel<<<(n4Xh + 255) / 256, 256>>>(X + (size_t)n4Xh * 4, 0,
                                                   n4Xh * 4, n4Xh);           // 5
    vq_gemm_kernel<<<N / 128, 256, SMEM_BYTES>>>();                           // 6 (ncu -s 5)
    vq_output_kernel<<<N / 8, 256>>>(X, C, outQ, outIdx, N);                  // 7
    vq_finalize_kernel<<<1, 256>>>(outScalars, N, K);                         // 8
}